// round 2
// baseline (speedup 1.0000x reference)
#include <cuda_runtime.h>
#include <cstdint>

#define NMAX 1000000
#define EMAX 1000000
#define HDIM 64
#define FIN  19
#define LN_EPS 1e-5f

// ---------------- device scratch (static: no runtime allocation) ----------------
__device__ float g_h[(size_t)NMAX * HDIM];        // node embeddings [N,64]
__device__ float g_delta[(size_t)NMAX * HDIM];    // compacted deltas [np,64]
__device__ int   g_cnt[NMAX];
__device__ int   g_row[NMAX];                     // CSR row starts (exclusive scan of cnt)
__device__ int   g_pos[NMAX];
__device__ int   g_children[EMAX];
__device__ int   g_plist[NMAX];                   // parents with >=1 child
__device__ int   g_nplist;
__device__ int   g_bsum[1024];
__device__ int   g_boff[1024];
__device__ int   g_is64;                          // 1 if index inputs are int64

__device__ __forceinline__ float leaky(float v) { return v > 0.f ? v : 0.01f * v; }

__device__ __forceinline__ float wsum(float v) {
#pragma unroll
    for (int o = 16; o; o >>= 1) v += __shfl_xor_sync(0xffffffffu, v, o);
    return v;
}

// Read index i from a buffer that is either int64 or int32, clamped to [0,n).
__device__ __forceinline__ int idx_at(const void* p, int i, int is64, int n) {
    long long v = is64 ? ((const long long*)p)[i] : (long long)((const int*)p)[i];
    unsigned u = (unsigned)v;
    return (u < (unsigned)n) ? (int)u : 0;
}

// ---------------- dtype detection (1 thread) ----------------
__global__ void detect_kernel(const unsigned* __restrict__ words, int nPairs) {
    if (blockIdx.x == 0 && threadIdx.x == 0) {
        int all0 = 1;
        int lim = nPairs < 128 ? nPairs : 128;
        for (int i = 0; i < lim; ++i)
            if (words[2 * i + 1] != 0u) { all0 = 0; break; }
        g_is64 = all0;
    }
}

// ---------------- CSR build ----------------
__global__ void zero_kernel(int n) {
    int i = blockIdx.x * blockDim.x + threadIdx.x;
    if (i < n) { g_cnt[i] = 0; g_pos[i] = 0; }
    if (i == 0) g_nplist = 0;
}

__global__ void hist_kernel(const void* __restrict__ ei, int E, int nN) {
    int is64 = g_is64;
    int e = blockIdx.x * blockDim.x + threadIdx.x;
    if (e < E) {
        int p = idx_at(ei, e, is64, nN);
        atomicAdd(&g_cnt[p], 1);
    }
}

// exclusive scan of g_cnt -> g_row (1024 elems/block), block sums -> g_bsum
__global__ void scan_cnt_kernel(int n) {
    __shared__ int s[256];
    int t = threadIdx.x;
    int base = blockIdx.x * 1024 + t * 4;
    int v0 = (base + 0 < n) ? g_cnt[base + 0] : 0;
    int v1 = (base + 1 < n) ? g_cnt[base + 1] : 0;
    int v2 = (base + 2 < n) ? g_cnt[base + 2] : 0;
    int v3 = (base + 3 < n) ? g_cnt[base + 3] : 0;
    int tsum = v0 + v1 + v2 + v3;
    s[t] = tsum; __syncthreads();
    for (int o = 1; o < 256; o <<= 1) {
        int add = (t >= o) ? s[t - o] : 0;
        __syncthreads();
        s[t] += add;
        __syncthreads();
    }
    int excl = s[t] - tsum;
    if (base + 0 < n) g_row[base + 0] = excl;
    if (base + 1 < n) g_row[base + 1] = excl + v0;
    if (base + 2 < n) g_row[base + 2] = excl + v0 + v1;
    if (base + 3 < n) g_row[base + 3] = excl + v0 + v1 + v2;
    if (t == 255) g_bsum[blockIdx.x] = s[255];
}

// exclusive scan of g_bsum -> g_boff (single block, up to 1024 elems)
__global__ void scan_bsum_kernel(int n) {
    __shared__ int s[256];
    int t = threadIdx.x;
    int base = t * 4;
    int v0 = (base + 0 < n) ? g_bsum[base + 0] : 0;
    int v1 = (base + 1 < n) ? g_bsum[base + 1] : 0;
    int v2 = (base + 2 < n) ? g_bsum[base + 2] : 0;
    int v3 = (base + 3 < n) ? g_bsum[base + 3] : 0;
    int tsum = v0 + v1 + v2 + v3;
    s[t] = tsum; __syncthreads();
    for (int o = 1; o < 256; o <<= 1) {
        int add = (t >= o) ? s[t - o] : 0;
        __syncthreads();
        s[t] += add;
        __syncthreads();
    }
    int excl = s[t] - tsum;
    if (base + 0 < n) g_boff[base + 0] = excl;
    if (base + 1 < n) g_boff[base + 1] = excl + v0;
    if (base + 2 < n) g_boff[base + 2] = excl + v0 + v1;
    if (base + 3 < n) g_boff[base + 3] = excl + v0 + v1 + v2;
}

// add block offsets and build compacted parent list (warp-aggregated append)
__global__ void addback_kernel(int n) {
    int i = blockIdx.x * blockDim.x + threadIdx.x;
    int c = (i < n) ? g_cnt[i] : 0;
    if (i < n) g_row[i] += g_boff[i >> 10];
    bool act = (c > 0);
    unsigned mask = __ballot_sync(0xffffffffu, act);
    if (act) {
        int lane = threadIdx.x & 31;
        int leader = __ffs(mask) - 1;
        int rank = __popc(mask & ((1u << lane) - 1u));
        int basep = 0;
        if (lane == leader) basep = atomicAdd(&g_nplist, __popc(mask));
        basep = __shfl_sync(mask, basep, leader);
        g_plist[basep + rank] = i;
    }
}

__global__ void scatter_kernel(const void* __restrict__ ei, int E, int nN) {
    int is64 = g_is64;
    int e = blockIdx.x * blockDim.x + threadIdx.x;
    if (e < E) {
        int p = idx_at(ei, e, is64, nN);
        int c = idx_at(ei, E + e, is64, nN);
        int pos = atomicAdd(&g_pos[p], 1);
        g_children[g_row[p] + pos] = c;
    }
}

// ---------------- embedding ----------------
// warp = 4 nodes; lane owns outputs (lane, lane+32). Weights in shared as
// k-pair float4 quads: (W[k][j], W[k][j+32], W[k+1][j], W[k+1][j+32]).
__global__ __launch_bounds__(256) void embed_kernel(
    const float* __restrict__ x, const float* __restrict__ pW, const float* __restrict__ pb,
    const float* __restrict__ eW, const float* __restrict__ eb,
    const float* __restrict__ gamma, const float* __restrict__ beta, int nN)
{
    __shared__ float4 s_pW[10 * 32];        // k padded to 20
    __shared__ float4 s_eW[2 * 32 * 32];    // [layer][kpair][lane]
    __shared__ float4 s_x[8][4][5];         // [warp][node][kquad], 20 floats/node
    __shared__ float4 s_h[8][4][16];        // [warp][node][kquad], 64 floats/node
    int tid = threadIdx.x;
    for (int i = tid; i < 10 * 32; i += 256) {
        int kp = i >> 5, l = i & 31;
        int k0 = 2 * kp, k1 = 2 * kp + 1;
        float a = (k0 < FIN) ? pW[k0 * 64 + l]      : 0.f;
        float b = (k0 < FIN) ? pW[k0 * 64 + l + 32] : 0.f;
        float c = (k1 < FIN) ? pW[k1 * 64 + l]      : 0.f;
        float d = (k1 < FIN) ? pW[k1 * 64 + l + 32] : 0.f;
        s_pW[i] = make_float4(a, b, c, d);
    }
    for (int i = tid; i < 2 * 32 * 32; i += 256) {
        int li = i >> 10, r = i & 1023, kp = r >> 5, l = r & 31;
        const float* W = eW + li * 4096;
        int k0 = 2 * kp;
        s_eW[i] = make_float4(W[k0 * 64 + l], W[k0 * 64 + l + 32],
                              W[(k0 + 1) * 64 + l], W[(k0 + 1) * 64 + l + 32]);
    }
    __syncthreads();

    int wid = tid >> 5, lane = tid & 31;
    float pbl = pb[lane], pbh = pb[lane + 32];
    float ebl[2], ebh[2], gl[2], ghi[2], bl[2], bh[2];
#pragma unroll
    for (int i2 = 0; i2 < 2; i2++) {
        ebl[i2] = eb[i2 * 64 + lane];    ebh[i2] = eb[i2 * 64 + lane + 32];
        gl[i2] = gamma[i2 * 64 + lane];  ghi[i2] = gamma[i2 * 64 + lane + 32];
        bl[i2] = beta[i2 * 64 + lane];   bh[i2] = beta[i2 * 64 + lane + 32];
    }
    float* sxf = (float*)&s_x[wid][0][0];   // 4 nodes * 20 floats
    float* shf = (float*)&s_h[wid][0][0];   // 4 nodes * 64 floats

    int nQ = (nN + 3) >> 2;
    for (int q = blockIdx.x * 8 + wid; q < nQ; q += gridDim.x * 8) {
        int n0 = q << 2;
        int rem = nN - n0;
        size_t base = (size_t)n0 * FIN;
        size_t lim = (size_t)nN * FIN;
        __syncwarp();
#pragma unroll
        for (int t2 = 0; t2 < 3; ++t2) {
            int idx = lane + 32 * t2;
            if (idx < 4 * FIN) {
                float v = (base + idx < lim) ? x[base + idx] : 0.f;
                int r = idx / FIN, kk = idx - r * FIN;
                sxf[r * 20 + kk] = v;
            }
        }
        if (lane < 4) sxf[lane * 20 + 19] = 0.f;
        __syncwarp();

        // input projection
        float al[4], ah[4];
#pragma unroll
        for (int r = 0; r < 4; r++) { al[r] = pbl; ah[r] = pbh; }
#pragma unroll
        for (int kq = 0; kq < 5; ++kq) {
            float4 w0 = s_pW[(2 * kq) * 32 + lane];
            float4 w1 = s_pW[(2 * kq + 1) * 32 + lane];
#pragma unroll
            for (int r = 0; r < 4; r++) {
                float4 xv = s_x[wid][r][kq];
                al[r] += xv.x * w0.x + xv.y * w0.z + xv.z * w1.x + xv.w * w1.z;
                ah[r] += xv.x * w0.y + xv.y * w0.w + xv.z * w1.y + xv.w * w1.w;
            }
        }
        float hl[4], hh[4];
#pragma unroll
        for (int r = 0; r < 4; r++) { hl[r] = leaky(al[r]); hh[r] = leaky(ah[r]); }

        // two residual + LN layers
#pragma unroll
        for (int li = 0; li < 2; ++li) {
#pragma unroll
            for (int r = 0; r < 4; r++) { shf[r * 64 + lane] = hl[r]; shf[r * 64 + lane + 32] = hh[r]; }
            __syncwarp();
            float tl[4], th[4];
#pragma unroll
            for (int r = 0; r < 4; r++) { tl[r] = ebl[li]; th[r] = ebh[li]; }
#pragma unroll
            for (int kq = 0; kq < 16; ++kq) {
                float4 w0 = s_eW[li * 1024 + (2 * kq) * 32 + lane];
                float4 w1 = s_eW[li * 1024 + (2 * kq + 1) * 32 + lane];
#pragma unroll
                for (int r = 0; r < 4; r++) {
                    float4 hv = s_h[wid][r][kq];
                    tl[r] += hv.x * w0.x + hv.y * w0.z + hv.z * w1.x + hv.w * w1.z;
                    th[r] += hv.x * w0.y + hv.y * w0.w + hv.z * w1.y + hv.w * w1.w;
                }
            }
#pragma unroll
            for (int r = 0; r < 4; r++) {
                float ul = hl[r] + leaky(tl[r]);
                float uh = hh[r] + leaky(th[r]);
                float s1 = wsum(ul + uh);
                float s2 = wsum(ul * ul + uh * uh);
                float mu = s1 * (1.f / 64.f);
                float var = s2 * (1.f / 64.f) - mu * mu;
                float inv = rsqrtf(var + LN_EPS);
                hl[r] = (ul - mu) * inv * gl[li] + bl[li];
                hh[r] = (uh - mu) * inv * ghi[li] + bh[li];
            }
            __syncwarp();
        }
#pragma unroll
        for (int r = 0; r < 4; r++) {
            if (r < rem) {
                g_h[(size_t)(n0 + r) * 64 + lane] = hl[r];
                g_h[(size_t)(n0 + r) * 64 + lane + 32] = hh[r];
            }
        }
    }
}

// ---------------- fused message passing (gather-mean + 2-layer MLP -> delta) ----------------
__global__ __launch_bounds__(256) void mp_kernel(
    const float* __restrict__ W1g, const float* __restrict__ b1g,
    const float* __restrict__ W2g, const float* __restrict__ b2g)
{
    __shared__ float4 s_W1[1024];
    __shared__ float4 s_W2[1024];
    __shared__ float4 s_hq[8][4][16];
    int tid = threadIdx.x;
    for (int i = tid; i < 1024; i += 256) {
        int kp = i >> 5, l = i & 31; int k0 = kp * 2;
        s_W1[i] = make_float4(W1g[k0 * 64 + l], W1g[k0 * 64 + l + 32],
                              W1g[(k0 + 1) * 64 + l], W1g[(k0 + 1) * 64 + l + 32]);
        s_W2[i] = make_float4(W2g[k0 * 64 + l], W2g[k0 * 64 + l + 32],
                              W2g[(k0 + 1) * 64 + l], W2g[(k0 + 1) * 64 + l + 32]);
    }
    __syncthreads();
    int wid = tid >> 5, lane = tid & 31;
    float b1l = b1g[lane], b1h = b1g[lane + 32];
    float b2l = b2g[lane], b2h = b2g[lane + 32];
    float* shf = (float*)&s_hq[wid][0][0];
    int np = g_nplist;
    int nQ = (np + 3) >> 2;
    for (int q = blockIdx.x * 8 + wid; q < nQ; q += gridDim.x * 8) {
        int i0 = q << 2;
        __syncwarp();
#pragma unroll
        for (int r = 0; r < 4; r++) {
            float ml = 0.f, mh = 0.f;
            if (i0 + r < np) {
                int p = g_plist[i0 + r];
                int st = g_row[p];
                int c = g_cnt[p];
                float sl = 0.f, sh = 0.f;
                for (int t = 0; t < c; ++t) {
                    int ch = g_children[st + t];
                    const float* hr = g_h + (size_t)ch * 64;
                    sl += hr[lane];
                    sh += hr[lane + 32];
                }
                float inv = 1.f / (float)c;
                ml = sl * inv; mh = sh * inv;
            }
            shf[r * 64 + lane] = ml;
            shf[r * 64 + lane + 32] = mh;
        }
        __syncwarp();
        float tl[4], th[4];
#pragma unroll
        for (int r = 0; r < 4; r++) { tl[r] = b1l; th[r] = b1h; }
#pragma unroll
        for (int kq = 0; kq < 16; ++kq) {
            float4 w0 = s_W1[(2 * kq) * 32 + lane];
            float4 w1 = s_W1[(2 * kq + 1) * 32 + lane];
#pragma unroll
            for (int r = 0; r < 4; r++) {
                float4 hv = s_hq[wid][r][kq];
                tl[r] += hv.x * w0.x + hv.y * w0.z + hv.z * w1.x + hv.w * w1.z;
                th[r] += hv.x * w0.y + hv.y * w0.w + hv.z * w1.y + hv.w * w1.w;
            }
        }
        __syncwarp();
#pragma unroll
        for (int r = 0; r < 4; r++) {
            shf[r * 64 + lane] = leaky(tl[r]);
            shf[r * 64 + lane + 32] = leaky(th[r]);
        }
        __syncwarp();
        float ol[4], oh[4];
#pragma unroll
        for (int r = 0; r < 4; r++) { ol[r] = b2l; oh[r] = b2h; }
#pragma unroll
        for (int kq = 0; kq < 16; ++kq) {
            float4 w0 = s_W2[(2 * kq) * 32 + lane];
            float4 w1 = s_W2[(2 * kq + 1) * 32 + lane];
#pragma unroll
            for (int r = 0; r < 4; r++) {
                float4 hv = s_hq[wid][r][kq];
                ol[r] += hv.x * w0.x + hv.y * w0.z + hv.z * w1.x + hv.w * w1.z;
                oh[r] += hv.x * w0.y + hv.y * w0.w + hv.z * w1.y + hv.w * w1.w;
            }
        }
#pragma unroll
        for (int r = 0; r < 4; r++) {
            if (i0 + r < np) {
                float* d = g_delta + (size_t)(i0 + r) * 64;
                d[lane] = ol[r];
                d[lane + 32] = oh[r];
            }
        }
    }
}

__global__ void apply_kernel() {
    int np = g_nplist;
    size_t total = (size_t)np * 64;
    size_t stride = (size_t)gridDim.x * blockDim.x;
    for (size_t i = (size_t)blockIdx.x * blockDim.x + threadIdx.x; i < total; i += stride) {
        int pi = (int)(i >> 6); int j = (int)(i & 63);
        int p = g_plist[pi];
        g_h[(size_t)p * 64 + j] += g_delta[i];
    }
}

// ---------------- score head + softmax (single block) ----------------
__global__ __launch_bounds__(256) void head_kernel(
    const void* __restrict__ cand,
    const float* __restrict__ W1g, const float* __restrict__ b1g,
    const float* __restrict__ W2g, const float* __restrict__ b2g,
    float* __restrict__ out, int K, int nN)
{
    __shared__ float4 s_W1[1024];
    __shared__ float4 s_hq[8][4][16];
    __shared__ float s_sc[1024];
    __shared__ float s_red[256];
    int tid = threadIdx.x;
    int is64 = g_is64;
    for (int i = tid; i < 1024; i += 256) {
        int kp = i >> 5, l = i & 31; int k0 = kp * 2;
        s_W1[i] = make_float4(W1g[k0 * 64 + l], W1g[k0 * 64 + l + 32],
                              W1g[(k0 + 1) * 64 + l], W1g[(k0 + 1) * 64 + l + 32]);
    }
    __syncthreads();
    int wid = tid >> 5, lane = tid & 31;
    float b1l = b1g[lane], b1h = b1g[lane + 32];
    float w2l = W2g[lane], w2h = W2g[lane + 32];
    float b2s = b2g[0];
    float* shf = (float*)&s_hq[wid][0][0];
    int nQ = (K + 3) >> 2;
    for (int q = wid; q < nQ; q += 8) {
        int c0 = q << 2;
        __syncwarp();
#pragma unroll
        for (int r = 0; r < 4; r++) {
            if (c0 + r < K) {
                int node = idx_at(cand, c0 + r, is64, nN);
                const float* hr = g_h + (size_t)node * 64;
                shf[r * 64 + lane] = hr[lane];
                shf[r * 64 + lane + 32] = hr[lane + 32];
            } else {
                shf[r * 64 + lane] = 0.f;
                shf[r * 64 + lane + 32] = 0.f;
            }
        }
        __syncwarp();
        float tl[4], th[4];
#pragma unroll
        for (int r = 0; r < 4; r++) { tl[r] = b1l; th[r] = b1h; }
#pragma unroll
        for (int kq = 0; kq < 16; ++kq) {
            float4 w0 = s_W1[(2 * kq) * 32 + lane];
            float4 w1 = s_W1[(2 * kq + 1) * 32 + lane];
#pragma unroll
            for (int r = 0; r < 4; r++) {
                float4 hv = s_hq[wid][r][kq];
                tl[r] += hv.x * w0.x + hv.y * w0.z + hv.z * w1.x + hv.w * w1.z;
                th[r] += hv.x * w0.y + hv.y * w0.w + hv.z * w1.y + hv.w * w1.w;
            }
        }
#pragma unroll
        for (int r = 0; r < 4; r++) {
            float s = leaky(tl[r]) * w2l + leaky(th[r]) * w2h;
            s = wsum(s) + b2s;
            if (lane == 0 && c0 + r < K) s_sc[c0 + r] = s;
        }
    }
    __syncthreads();
    // softmax over K
    float m = -3.4e38f;
    for (int i = tid; i < K; i += 256) m = fmaxf(m, s_sc[i]);
    s_red[tid] = m; __syncthreads();
    for (int o = 128; o; o >>= 1) { if (tid < o) s_red[tid] = fmaxf(s_red[tid], s_red[tid + o]); __syncthreads(); }
    m = s_red[0];
    __syncthreads();
    float sum = 0.f;
    for (int i = tid; i < K; i += 256) { float e = expf(s_sc[i] - m); s_sc[i] = e; sum += e; }
    s_red[tid] = sum; __syncthreads();
    for (int o = 128; o; o >>= 1) { if (tid < o) s_red[tid] += s_red[tid + o]; __syncthreads(); }
    float invT = 1.f / s_red[0];
    for (int i = tid; i < K; i += 256) out[i] = s_sc[i] * invT;
}

// ---------------- launch ----------------
extern "C" void kernel_launch(void* const* d_in, const int* in_sizes, int n_in,
                              void* d_out, int out_size) {
    const float* x     = (const float*)d_in[0];
    const void*  ei    = d_in[1];
    const void*  cand  = d_in[2];
    const float* pW    = (const float*)d_in[3];
    const float* pb    = (const float*)d_in[4];
    const float* eW    = (const float*)d_in[5];
    const float* eb    = (const float*)d_in[6];
    const float* gamma = (const float*)d_in[7];
    const float* beta  = (const float*)d_in[8];
    const float* sW1   = (const float*)d_in[9];
    const float* sb1   = (const float*)d_in[10];
    const float* sW2   = (const float*)d_in[11];
    const float* sb2   = (const float*)d_in[12];
    const float* hW1   = (const float*)d_in[13];
    const float* hb1   = (const float*)d_in[14];
    const float* hW2   = (const float*)d_in[15];
    const float* hb2   = (const float*)d_in[16];

    int nN = in_sizes[0] / FIN;
    int E  = in_sizes[1] / 2;
    int K  = in_sizes[2];

    int nb256 = (nN + 255) / 256;
    int eb256 = (E + 255) / 256;
    int scanBlocks = (nN + 1023) / 1024;

    // detect int64 vs int32 index dtype
    detect_kernel<<<1, 32>>>((const unsigned*)ei, E);

    // CSR build
    zero_kernel<<<nb256, 256>>>(nN);
    hist_kernel<<<eb256, 256>>>(ei, E, nN);
    scan_cnt_kernel<<<scanBlocks, 256>>>(nN);
    scan_bsum_kernel<<<1, 256>>>(scanBlocks);
    addback_kernel<<<nb256, 256>>>(nN);
    scatter_kernel<<<eb256, 256>>>(ei, E, nN);

    // embedding
    embed_kernel<<<2048, 256>>>(x, pW, pb, eW, eb, gamma, beta, nN);

    // 3 message-passing iterations
    for (int it = 0; it < 3; ++it) {
        mp_kernel<<<2048, 256>>>(sW1 + it * 4096, sb1 + it * 64,
                                 sW2 + it * 4096, sb2 + it * 64);
        apply_kernel<<<4096, 256>>>();
    }

    // score head + softmax
    head_kernel<<<1, 256>>>(cand, hW1, hb1, hW2, hb2, (float*)d_out, K, nN);
}

// round 3
// speedup vs baseline: 1.0098x; 1.0098x over previous
#include <cuda_runtime.h>
#include <cstdint>

#define NMAX 1000000
#define EMAX 1000000
#define HDIM 64
#define FIN  19
#define LN_EPS 1e-5f

// ---------------- device scratch ----------------
__device__ float g_h[(size_t)NMAX * HDIM];
__device__ float g_delta[(size_t)NMAX * HDIM];
__device__ int   g_cnt[NMAX];
__device__ int   g_row[NMAX];
__device__ int   g_pos[NMAX];
__device__ int   g_children[EMAX];
__device__ int   g_plist[NMAX];
__device__ int   g_nplist;
__device__ int   g_bsum[1024];
__device__ int   g_boff[1024];
__device__ int   g_is64;

__device__ __forceinline__ float leaky(float v) { return v > 0.f ? v : 0.01f * v; }

__device__ __forceinline__ float wsum(float v) {
#pragma unroll
    for (int o = 16; o; o >>= 1) v += __shfl_xor_sync(0xffffffffu, v, o);
    return v;
}

// ---------------- packed f32x2 helpers (FFMA2 path; ptxas won't emit from C++) ----
__device__ __forceinline__ unsigned long long pack2(float lo, float hi) {
    unsigned long long d;
    asm("mov.b64 %0, {%1, %2};" : "=l"(d) : "r"(__float_as_uint(lo)), "r"(__float_as_uint(hi)));
    return d;
}
__device__ __forceinline__ unsigned long long dup2(float v) {
    unsigned long long d;
    unsigned u = __float_as_uint(v);
    asm("mov.b64 %0, {%1, %1};" : "=l"(d) : "r"(u));
    return d;
}
__device__ __forceinline__ void unpack2(unsigned long long v, float& lo, float& hi) {
    unsigned a, b;
    asm("mov.b64 {%0, %1}, %2;" : "=r"(a), "=r"(b) : "l"(v));
    lo = __uint_as_float(a); hi = __uint_as_float(b);
}
__device__ __forceinline__ void fma2(unsigned long long& a, unsigned long long b, unsigned long long c) {
    asm("fma.rn.f32x2 %0, %1, %2, %0;" : "+l"(a) : "l"(b), "l"(c));
}
__device__ __forceinline__ void add2(unsigned long long& a, unsigned long long b) {
    asm("add.rn.f32x2 %0, %0, %1;" : "+l"(a) : "l"(b));
}
__device__ __forceinline__ void mul2(unsigned long long& a, unsigned long long b) {
    asm("mul.rn.f32x2 %0, %0, %1;" : "+l"(a) : "l"(b));
}

__device__ __forceinline__ int idx_at(const void* p, int i, int is64, int n) {
    long long v = is64 ? ((const long long*)p)[i] : (long long)((const int*)p)[i];
    unsigned u = (unsigned)v;
    return (u < (unsigned)n) ? (int)u : 0;
}

// ---------------- dtype detection ----------------
__global__ void detect_kernel(const unsigned* __restrict__ words, int nPairs) {
    if (blockIdx.x == 0 && threadIdx.x == 0) {
        int all0 = 1;
        int lim = nPairs < 128 ? nPairs : 128;
        for (int i = 0; i < lim; ++i)
            if (words[2 * i + 1] != 0u) { all0 = 0; break; }
        g_is64 = all0;
    }
}

// ---------------- CSR build ----------------
__global__ void zero_kernel(int n) {
    int i = blockIdx.x * blockDim.x + threadIdx.x;
    if (i < n) { g_cnt[i] = 0; g_pos[i] = 0; }
    if (i == 0) g_nplist = 0;
}

__global__ void hist_kernel(const void* __restrict__ ei, int E, int nN) {
    int is64 = g_is64;
    int e = blockIdx.x * blockDim.x + threadIdx.x;
    if (e < E) atomicAdd(&g_cnt[idx_at(ei, e, is64, nN)], 1);
}

__global__ void scan_cnt_kernel(int n) {
    __shared__ int s[256];
    int t = threadIdx.x;
    int base = blockIdx.x * 1024 + t * 4;
    int v0 = (base + 0 < n) ? g_cnt[base + 0] : 0;
    int v1 = (base + 1 < n) ? g_cnt[base + 1] : 0;
    int v2 = (base + 2 < n) ? g_cnt[base + 2] : 0;
    int v3 = (base + 3 < n) ? g_cnt[base + 3] : 0;
    int tsum = v0 + v1 + v2 + v3;
    s[t] = tsum; __syncthreads();
    for (int o = 1; o < 256; o <<= 1) {
        int add = (t >= o) ? s[t - o] : 0;
        __syncthreads();
        s[t] += add;
        __syncthreads();
    }
    int excl = s[t] - tsum;
    if (base + 0 < n) g_row[base + 0] = excl;
    if (base + 1 < n) g_row[base + 1] = excl + v0;
    if (base + 2 < n) g_row[base + 2] = excl + v0 + v1;
    if (base + 3 < n) g_row[base + 3] = excl + v0 + v1 + v2;
    if (t == 255) g_bsum[blockIdx.x] = s[255];
}

__global__ void scan_bsum_kernel(int n) {
    __shared__ int s[256];
    int t = threadIdx.x;
    int base = t * 4;
    int v0 = (base + 0 < n) ? g_bsum[base + 0] : 0;
    int v1 = (base + 1 < n) ? g_bsum[base + 1] : 0;
    int v2 = (base + 2 < n) ? g_bsum[base + 2] : 0;
    int v3 = (base + 3 < n) ? g_bsum[base + 3] : 0;
    int tsum = v0 + v1 + v2 + v3;
    s[t] = tsum; __syncthreads();
    for (int o = 1; o < 256; o <<= 1) {
        int add = (t >= o) ? s[t - o] : 0;
        __syncthreads();
        s[t] += add;
        __syncthreads();
    }
    int excl = s[t] - tsum;
    if (base + 0 < n) g_boff[base + 0] = excl;
    if (base + 1 < n) g_boff[base + 1] = excl + v0;
    if (base + 2 < n) g_boff[base + 2] = excl + v0 + v1;
    if (base + 3 < n) g_boff[base + 3] = excl + v0 + v1 + v2;
}

__global__ void addback_kernel(int n) {
    int i = blockIdx.x * blockDim.x + threadIdx.x;
    int c = (i < n) ? g_cnt[i] : 0;
    if (i < n) g_row[i] += g_boff[i >> 10];
    bool act = (c > 0);
    unsigned mask = __ballot_sync(0xffffffffu, act);
    if (act) {
        int lane = threadIdx.x & 31;
        int leader = __ffs(mask) - 1;
        int rank = __popc(mask & ((1u << lane) - 1u));
        int basep = 0;
        if (lane == leader) basep = atomicAdd(&g_nplist, __popc(mask));
        basep = __shfl_sync(mask, basep, leader);
        g_plist[basep + rank] = i;
    }
}

__global__ void scatter_kernel(const void* __restrict__ ei, int E, int nN) {
    int is64 = g_is64;
    int e = blockIdx.x * blockDim.x + threadIdx.x;
    if (e < E) {
        int p = idx_at(ei, e, is64, nN);
        int c = idx_at(ei, E + e, is64, nN);
        int pos = atomicAdd(&g_pos[p], 1);
        g_children[g_row[p] + pos] = c;
    }
}

// ---------------- embedding (packed f32x2, 4 warps/block, 8 nodes/warp) ------
__global__ __launch_bounds__(128) void embed_kernel(
    const float* __restrict__ x, const float* __restrict__ pW, const float* __restrict__ pb,
    const float* __restrict__ eW, const float* __restrict__ eb,
    const float* __restrict__ gamma, const float* __restrict__ beta, int nN)
{
    __shared__ float4 s_pW[10 * 32];        // proj weights, k padded to 20
    __shared__ float4 s_eW[2 * 32 * 32];    // [layer][kpair][lane]
    __shared__ float4 s_x[4][8][5];         // [warp][node][kquad]
    __shared__ float4 s_h[4][8][16];        // [warp][node][kquad]
    int tid = threadIdx.x;
    for (int i = tid; i < 10 * 32; i += 128) {
        int kp = i >> 5, l = i & 31;
        int k0 = 2 * kp, k1 = 2 * kp + 1;
        float a = (k0 < FIN) ? pW[k0 * 64 + l]      : 0.f;
        float b = (k0 < FIN) ? pW[k0 * 64 + l + 32] : 0.f;
        float c = (k1 < FIN) ? pW[k1 * 64 + l]      : 0.f;
        float d = (k1 < FIN) ? pW[k1 * 64 + l + 32] : 0.f;
        s_pW[i] = make_float4(a, b, c, d);
    }
    for (int i = tid; i < 2 * 32 * 32; i += 128) {
        int li = i >> 10, r = i & 1023, kp = r >> 5, l = r & 31;
        const float* W = eW + li * 4096;
        int k0 = 2 * kp;
        s_eW[i] = make_float4(W[k0 * 64 + l], W[k0 * 64 + l + 32],
                              W[(k0 + 1) * 64 + l], W[(k0 + 1) * 64 + l + 32]);
    }
    __syncthreads();

    int wid = tid >> 5, lane = tid & 31;
    unsigned long long pb2 = pack2(pb[lane], pb[lane + 32]);
    unsigned long long eb2[2];
    float gl[2], ghi[2], bl[2], bh[2];
#pragma unroll
    for (int i2 = 0; i2 < 2; i2++) {
        eb2[i2] = pack2(eb[i2 * 64 + lane], eb[i2 * 64 + lane + 32]);
        gl[i2] = gamma[i2 * 64 + lane];  ghi[i2] = gamma[i2 * 64 + lane + 32];
        bl[i2] = beta[i2 * 64 + lane];   bh[i2] = beta[i2 * 64 + lane + 32];
    }
    float* sxf = (float*)&s_x[wid][0][0];   // 8 nodes * 20 floats
    float* shf = (float*)&s_h[wid][0][0];   // 8 nodes * 64 floats

    int nG = (nN + 7) >> 3;
    for (int g = blockIdx.x * 4 + wid; g < nG; g += gridDim.x * 4) {
        int n0 = g << 3;
        int rem = nN - n0;
        size_t base = (size_t)n0 * FIN;
        size_t lim = (size_t)nN * FIN;
        __syncwarp();
#pragma unroll
        for (int t2 = 0; t2 < 5; ++t2) {
            int idx = lane + 32 * t2;
            if (idx < 8 * FIN) {
                float v = (base + idx < lim) ? x[base + idx] : 0.f;
                int r = idx / FIN, kk = idx - r * FIN;
                sxf[r * 20 + kk] = v;
            }
        }
        if (lane < 8) sxf[lane * 20 + 19] = 0.f;
        __syncwarp();

        // input projection
        unsigned long long acc[8];
#pragma unroll
        for (int r = 0; r < 8; r++) acc[r] = pb2;
#pragma unroll
        for (int kq = 0; kq < 5; ++kq) {
            ulonglong2 w0 = *(const ulonglong2*)&s_pW[(2 * kq) * 32 + lane];
            ulonglong2 w1 = *(const ulonglong2*)&s_pW[(2 * kq + 1) * 32 + lane];
#pragma unroll
            for (int r = 0; r < 8; r++) {
                float4 xv = s_x[wid][r][kq];
                fma2(acc[r], w0.x, dup2(xv.x));
                fma2(acc[r], w0.y, dup2(xv.y));
                fma2(acc[r], w1.x, dup2(xv.z));
                fma2(acc[r], w1.y, dup2(xv.w));
            }
        }
        float hl[8], hh[8];
#pragma unroll
        for (int r = 0; r < 8; r++) {
            float a, b; unpack2(acc[r], a, b);
            hl[r] = leaky(a); hh[r] = leaky(b);
        }

        // two residual + LN layers
#pragma unroll
        for (int li = 0; li < 2; ++li) {
#pragma unroll
            for (int r = 0; r < 8; r++) { shf[r * 64 + lane] = hl[r]; shf[r * 64 + lane + 32] = hh[r]; }
            __syncwarp();
#pragma unroll
            for (int r = 0; r < 8; r++) acc[r] = eb2[li];
#pragma unroll
            for (int kq = 0; kq < 16; ++kq) {
                ulonglong2 w0 = *(const ulonglong2*)&s_eW[li * 1024 + (2 * kq) * 32 + lane];
                ulonglong2 w1 = *(const ulonglong2*)&s_eW[li * 1024 + (2 * kq + 1) * 32 + lane];
#pragma unroll
                for (int r = 0; r < 8; r++) {
                    float4 hv = s_h[wid][r][kq];
                    fma2(acc[r], w0.x, dup2(hv.x));
                    fma2(acc[r], w0.y, dup2(hv.y));
                    fma2(acc[r], w1.x, dup2(hv.z));
                    fma2(acc[r], w1.y, dup2(hv.w));
                }
            }
#pragma unroll
            for (int r = 0; r < 8; r++) {
                float tl, th; unpack2(acc[r], tl, th);
                float ul = hl[r] + leaky(tl);
                float uh = hh[r] + leaky(th);
                float s1 = wsum(ul + uh);
                float s2 = wsum(ul * ul + uh * uh);
                float mu = s1 * (1.f / 64.f);
                float var = s2 * (1.f / 64.f) - mu * mu;
                float inv = rsqrtf(var + LN_EPS);
                hl[r] = (ul - mu) * inv * gl[li] + bl[li];
                hh[r] = (uh - mu) * inv * ghi[li] + bh[li];
            }
            __syncwarp();
        }
#pragma unroll
        for (int r = 0; r < 8; r++) {
            if (r < rem) {
                g_h[(size_t)(n0 + r) * 64 + lane] = hl[r];
                g_h[(size_t)(n0 + r) * 64 + lane + 32] = hh[r];
            }
        }
    }
}

// ---------------- fused message passing (packed f32x2) ----------------
__global__ __launch_bounds__(128) void mp_kernel(
    const float* __restrict__ W1g, const float* __restrict__ b1g,
    const float* __restrict__ W2g, const float* __restrict__ b2g)
{
    __shared__ float4 s_W1[1024];
    __shared__ float4 s_W2[1024];
    __shared__ float4 s_hq[4][8][16];
    int tid = threadIdx.x;
    for (int i = tid; i < 1024; i += 128) {
        int kp = i >> 5, l = i & 31; int k0 = kp * 2;
        s_W1[i] = make_float4(W1g[k0 * 64 + l], W1g[k0 * 64 + l + 32],
                              W1g[(k0 + 1) * 64 + l], W1g[(k0 + 1) * 64 + l + 32]);
        s_W2[i] = make_float4(W2g[k0 * 64 + l], W2g[k0 * 64 + l + 32],
                              W2g[(k0 + 1) * 64 + l], W2g[(k0 + 1) * 64 + l + 32]);
    }
    __syncthreads();
    int wid = tid >> 5, lane = tid & 31;
    unsigned long long b12 = pack2(b1g[lane], b1g[lane + 32]);
    unsigned long long b22 = pack2(b2g[lane], b2g[lane + 32]);
    float* shf = (float*)&s_hq[wid][0][0];
    int np = g_nplist;
    int nG = (np + 7) >> 3;
    for (int g = blockIdx.x * 4 + wid; g < nG; g += gridDim.x * 4) {
        int i0 = g << 3;
        __syncwarp();
#pragma unroll
        for (int r = 0; r < 8; r++) {
            unsigned long long sum = 0ull;   // packed (elem 2*lane, 2*lane+1)
            if (i0 + r < np) {
                int p = g_plist[i0 + r];
                int st = g_row[p];
                int c = g_cnt[p];
                for (int t = 0; t < c; ++t) {
                    int ch = g_children[st + t];
                    unsigned long long hv = *(const unsigned long long*)(g_h + (size_t)ch * 64 + 2 * lane);
                    add2(sum, hv);
                }
                mul2(sum, dup2(1.f / (float)c));
            }
            *(unsigned long long*)(shf + r * 64 + 2 * lane) = sum;
        }
        __syncwarp();
        unsigned long long acc[8];
#pragma unroll
        for (int r = 0; r < 8; r++) acc[r] = b12;
#pragma unroll
        for (int kq = 0; kq < 16; ++kq) {
            ulonglong2 w0 = *(const ulonglong2*)&s_W1[(2 * kq) * 32 + lane];
            ulonglong2 w1 = *(const ulonglong2*)&s_W1[(2 * kq + 1) * 32 + lane];
#pragma unroll
            for (int r = 0; r < 8; r++) {
                float4 hv = s_hq[wid][r][kq];
                fma2(acc[r], w0.x, dup2(hv.x));
                fma2(acc[r], w0.y, dup2(hv.y));
                fma2(acc[r], w1.x, dup2(hv.z));
                fma2(acc[r], w1.y, dup2(hv.w));
            }
        }
        __syncwarp();
#pragma unroll
        for (int r = 0; r < 8; r++) {
            float a, b; unpack2(acc[r], a, b);
            shf[r * 64 + lane] = leaky(a);
            shf[r * 64 + lane + 32] = leaky(b);
        }
        __syncwarp();
#pragma unroll
        for (int r = 0; r < 8; r++) acc[r] = b22;
#pragma unroll
        for (int kq = 0; kq < 16; ++kq) {
            ulonglong2 w0 = *(const ulonglong2*)&s_W2[(2 * kq) * 32 + lane];
            ulonglong2 w1 = *(const ulonglong2*)&s_W2[(2 * kq + 1) * 32 + lane];
#pragma unroll
            for (int r = 0; r < 8; r++) {
                float4 hv = s_hq[wid][r][kq];
                fma2(acc[r], w0.x, dup2(hv.x));
                fma2(acc[r], w0.y, dup2(hv.y));
                fma2(acc[r], w1.x, dup2(hv.z));
                fma2(acc[r], w1.y, dup2(hv.w));
            }
        }
#pragma unroll
        for (int r = 0; r < 8; r++) {
            if (i0 + r < np) {
                float a, b; unpack2(acc[r], a, b);
                float* d = g_delta + (size_t)(i0 + r) * 64;
                d[lane] = a;
                d[lane + 32] = b;
            }
        }
    }
}

// ---------------- apply: warp per parent, float2 ----------------
__global__ void apply_kernel() {
    int np = g_nplist;
    int lane = threadIdx.x & 31;
    int w = (blockIdx.x * blockDim.x + threadIdx.x) >> 5;
    int nw = (gridDim.x * blockDim.x) >> 5;
    for (int pi = w; pi < np; pi += nw) {
        int p = g_plist[pi];
        const float2* dr = (const float2*)(g_delta + (size_t)pi * 64);
        float2* hr = (float2*)(g_h + (size_t)p * 64);
        float2 d = dr[lane];
        float2 h = hr[lane];
        h.x += d.x; h.y += d.y;
        hr[lane] = h;
    }
}

// ---------------- score head + softmax (single block) ----------------
__global__ __launch_bounds__(256) void head_kernel(
    const void* __restrict__ cand,
    const float* __restrict__ W1g, const float* __restrict__ b1g,
    const float* __restrict__ W2g, const float* __restrict__ b2g,
    float* __restrict__ out, int K, int nN)
{
    __shared__ float4 s_W1[1024];
    __shared__ float4 s_hq[8][4][16];
    __shared__ float s_sc[1024];
    __shared__ float s_red[256];
    int tid = threadIdx.x;
    int is64 = g_is64;
    for (int i = tid; i < 1024; i += 256) {
        int kp = i >> 5, l = i & 31; int k0 = kp * 2;
        s_W1[i] = make_float4(W1g[k0 * 64 + l], W1g[k0 * 64 + l + 32],
                              W1g[(k0 + 1) * 64 + l], W1g[(k0 + 1) * 64 + l + 32]);
    }
    __syncthreads();
    int wid = tid >> 5, lane = tid & 31;
    float b1l = b1g[lane], b1h = b1g[lane + 32];
    float w2l = W2g[lane], w2h = W2g[lane + 32];
    float b2s = b2g[0];
    float* shf = (float*)&s_hq[wid][0][0];
    int nQ = (K + 3) >> 2;
    for (int q = wid; q < nQ; q += 8) {
        int c0 = q << 2;
        __syncwarp();
#pragma unroll
        for (int r = 0; r < 4; r++) {
            if (c0 + r < K) {
                int node = idx_at(cand, c0 + r, is64, nN);
                const float* hr = g_h + (size_t)node * 64;
                shf[r * 64 + lane] = hr[lane];
                shf[r * 64 + lane + 32] = hr[lane + 32];
            } else {
                shf[r * 64 + lane] = 0.f;
                shf[r * 64 + lane + 32] = 0.f;
            }
        }
        __syncwarp();
        float tl[4], th[4];
#pragma unroll
        for (int r = 0; r < 4; r++) { tl[r] = b1l; th[r] = b1h; }
#pragma unroll
        for (int kq = 0; kq < 16; ++kq) {
            float4 w0 = s_W1[(2 * kq) * 32 + lane];
            float4 w1 = s_W1[(2 * kq + 1) * 32 + lane];
#pragma unroll
            for (int r = 0; r < 4; r++) {
                float4 hv = s_hq[wid][r][kq];
                tl[r] += hv.x * w0.x + hv.y * w0.z + hv.z * w1.x + hv.w * w1.z;
                th[r] += hv.x * w0.y + hv.y * w0.w + hv.z * w1.y + hv.w * w1.w;
            }
        }
#pragma unroll
        for (int r = 0; r < 4; r++) {
            float s = leaky(tl[r]) * w2l + leaky(th[r]) * w2h;
            s = wsum(s) + b2s;
            if (lane == 0 && c0 + r < K) s_sc[c0 + r] = s;
        }
    }
    __syncthreads();
    float m = -3.4e38f;
    for (int i = tid; i < K; i += 256) m = fmaxf(m, s_sc[i]);
    s_red[tid] = m; __syncthreads();
    for (int o = 128; o; o >>= 1) { if (tid < o) s_red[tid] = fmaxf(s_red[tid], s_red[tid + o]); __syncthreads(); }
    m = s_red[0];
    __syncthreads();
    float sum = 0.f;
    for (int i = tid; i < K; i += 256) { float e = expf(s_sc[i] - m); s_sc[i] = e; sum += e; }
    s_red[tid] = sum; __syncthreads();
    for (int o = 128; o; o >>= 1) { if (tid < o) s_red[tid] += s_red[tid + o]; __syncthreads(); }
    float invT = 1.f / s_red[0];
    for (int i = tid; i < K; i += 256) out[i] = s_sc[i] * invT;
}

// ---------------- launch ----------------
extern "C" void kernel_launch(void* const* d_in, const int* in_sizes, int n_in,
                              void* d_out, int out_size) {
    const float* x     = (const float*)d_in[0];
    const void*  ei    = d_in[1];
    const void*  cand  = d_in[2];
    const float* pW    = (const float*)d_in[3];
    const float* pb    = (const float*)d_in[4];
    const float* eW    = (const float*)d_in[5];
    const float* eb    = (const float*)d_in[6];
    const float* gamma = (const float*)d_in[7];
    const float* beta  = (const float*)d_in[8];
    const float* sW1   = (const float*)d_in[9];
    const float* sb1   = (const float*)d_in[10];
    const float* sW2   = (const float*)d_in[11];
    const float* sb2   = (const float*)d_in[12];
    const float* hW1   = (const float*)d_in[13];
    const float* hb1   = (const float*)d_in[14];
    const float* hW2   = (const float*)d_in[15];
    const float* hb2   = (const float*)d_in[16];

    int nN = in_sizes[0] / FIN;
    int E  = in_sizes[1] / 2;
    int K  = in_sizes[2];

    int nb256 = (nN + 255) / 256;
    int eb256 = (E + 255) / 256;
    int scanBlocks = (nN + 1023) / 1024;

    detect_kernel<<<1, 32>>>((const unsigned*)ei, E);

    zero_kernel<<<nb256, 256>>>(nN);
    hist_kernel<<<eb256, 256>>>(ei, E, nN);
    scan_cnt_kernel<<<scanBlocks, 256>>>(nN);
    scan_bsum_kernel<<<1, 256>>>(scanBlocks);
    addback_kernel<<<nb256, 256>>>(nN);
    scatter_kernel<<<eb256, 256>>>(ei, E, nN);

    embed_kernel<<<592, 128>>>(x, pW, pb, eW, eb, gamma, beta, nN);

    for (int it = 0; it < 3; ++it) {
        mp_kernel<<<740, 128>>>(sW1 + it * 4096, sb1 + it * 64,
                                sW2 + it * 4096, sb2 + it * 64);
        apply_kernel<<<2048, 256>>>();
    }

    head_kernel<<<1, 256>>>(cand, hW1, hb1, hW2, hb2, (float*)d_out, K, nN);
}

// round 4
// speedup vs baseline: 1.2650x; 1.2527x over previous
#include <cuda_runtime.h>
#include <cstdint>

#define NMAX 1000000
#define EMAX 1000000
#define HDIM 64
#define FIN  19
#define LN_EPS 1e-5f

// ---------------- device scratch ----------------
__device__ float g_h[(size_t)NMAX * HDIM];
__device__ float g_delta[(size_t)NMAX * HDIM];
__device__ int   g_cnt[NMAX];
__device__ int   g_row[NMAX];
__device__ int   g_pos[NMAX];
__device__ int   g_children[EMAX];
__device__ int   g_plist[NMAX];
__device__ int   g_nplist;
__device__ int   g_bsum[1024];
__device__ int   g_boff[1024];
__device__ int   g_is64;

__device__ __forceinline__ float leaky(float v) { return v > 0.f ? v : 0.01f * v; }

__device__ __forceinline__ float wsum(float v) {
#pragma unroll
    for (int o = 16; o; o >>= 1) v += __shfl_xor_sync(0xffffffffu, v, o);
    return v;
}

// ---------------- packed f32x2 helpers ----------------
__device__ __forceinline__ unsigned long long pack2(float lo, float hi) {
    unsigned long long d;
    asm("mov.b64 %0, {%1, %2};" : "=l"(d) : "r"(__float_as_uint(lo)), "r"(__float_as_uint(hi)));
    return d;
}
__device__ __forceinline__ unsigned long long dup2(float v) {
    unsigned long long d;
    unsigned u = __float_as_uint(v);
    asm("mov.b64 %0, {%1, %1};" : "=l"(d) : "r"(u));
    return d;
}
__device__ __forceinline__ void unpack2(unsigned long long v, float& lo, float& hi) {
    unsigned a, b;
    asm("mov.b64 {%0, %1}, %2;" : "=r"(a), "=r"(b) : "l"(v));
    lo = __uint_as_float(a); hi = __uint_as_float(b);
}
__device__ __forceinline__ void fma2(unsigned long long& a, unsigned long long b, unsigned long long c) {
    asm("fma.rn.f32x2 %0, %1, %2, %0;" : "+l"(a) : "l"(b), "l"(c));
}
__device__ __forceinline__ void add2(unsigned long long& a, unsigned long long b) {
    asm("add.rn.f32x2 %0, %0, %1;" : "+l"(a) : "l"(b));
}
__device__ __forceinline__ void mul2(unsigned long long& a, unsigned long long b) {
    asm("mul.rn.f32x2 %0, %0, %1;" : "+l"(a) : "l"(b));
}

__device__ __forceinline__ int idx_at(const void* p, int i, int is64, int n) {
    long long v = is64 ? ((const long long*)p)[i] : (long long)((const int*)p)[i];
    unsigned u = (unsigned)v;
    return (u < (unsigned)n) ? (int)u : 0;
}

// ---------------- dtype detection (parallel: 256 threads, 1 pass) ------------
__global__ void detect_kernel(const unsigned* __restrict__ words, int nPairs) {
    __shared__ int flag;
    if (threadIdx.x == 0) flag = 0;
    __syncthreads();
    int lim = nPairs < 256 ? nPairs : 256;
    int i = threadIdx.x;
    if (i < lim && words[2 * i + 1] != 0u) flag = 1;
    __syncthreads();
    if (threadIdx.x == 0) g_is64 = (flag == 0);
}

// ---------------- CSR build ----------------
__global__ void zero_kernel(int n) {
    int i = blockIdx.x * blockDim.x + threadIdx.x;
    if (i < n) { g_cnt[i] = 0; g_pos[i] = 0; }
    if (i == 0) g_nplist = 0;
}

__global__ void hist_kernel(const void* __restrict__ ei, int E, int nN) {
    int is64 = g_is64;
    int e = blockIdx.x * blockDim.x + threadIdx.x;
    if (e < E) atomicAdd(&g_cnt[idx_at(ei, e, is64, nN)], 1);
}

__global__ void scan_cnt_kernel(int n) {
    __shared__ int s[256];
    int t = threadIdx.x;
    int base = blockIdx.x * 1024 + t * 4;
    int v0 = (base + 0 < n) ? g_cnt[base + 0] : 0;
    int v1 = (base + 1 < n) ? g_cnt[base + 1] : 0;
    int v2 = (base + 2 < n) ? g_cnt[base + 2] : 0;
    int v3 = (base + 3 < n) ? g_cnt[base + 3] : 0;
    int tsum = v0 + v1 + v2 + v3;
    s[t] = tsum; __syncthreads();
    for (int o = 1; o < 256; o <<= 1) {
        int add = (t >= o) ? s[t - o] : 0;
        __syncthreads();
        s[t] += add;
        __syncthreads();
    }
    int excl = s[t] - tsum;
    if (base + 0 < n) g_row[base + 0] = excl;
    if (base + 1 < n) g_row[base + 1] = excl + v0;
    if (base + 2 < n) g_row[base + 2] = excl + v0 + v1;
    if (base + 3 < n) g_row[base + 3] = excl + v0 + v1 + v2;
    if (t == 255) g_bsum[blockIdx.x] = s[255];
}

__global__ void scan_bsum_kernel(int n) {
    __shared__ int s[256];
    int t = threadIdx.x;
    int base = t * 4;
    int v0 = (base + 0 < n) ? g_bsum[base + 0] : 0;
    int v1 = (base + 1 < n) ? g_bsum[base + 1] : 0;
    int v2 = (base + 2 < n) ? g_bsum[base + 2] : 0;
    int v3 = (base + 3 < n) ? g_bsum[base + 3] : 0;
    int tsum = v0 + v1 + v2 + v3;
    s[t] = tsum; __syncthreads();
    for (int o = 1; o < 256; o <<= 1) {
        int add = (t >= o) ? s[t - o] : 0;
        __syncthreads();
        s[t] += add;
        __syncthreads();
    }
    int excl = s[t] - tsum;
    if (base + 0 < n) g_boff[base + 0] = excl;
    if (base + 1 < n) g_boff[base + 1] = excl + v0;
    if (base + 2 < n) g_boff[base + 2] = excl + v0 + v1;
    if (base + 3 < n) g_boff[base + 3] = excl + v0 + v1 + v2;
}

__global__ void addback_kernel(int n) {
    int i = blockIdx.x * blockDim.x + threadIdx.x;
    int c = (i < n) ? g_cnt[i] : 0;
    if (i < n) g_row[i] += g_boff[i >> 10];
    bool act = (c > 0);
    unsigned mask = __ballot_sync(0xffffffffu, act);
    if (act) {
        int lane = threadIdx.x & 31;
        int leader = __ffs(mask) - 1;
        int rank = __popc(mask & ((1u << lane) - 1u));
        int basep = 0;
        if (lane == leader) basep = atomicAdd(&g_nplist, __popc(mask));
        basep = __shfl_sync(mask, basep, leader);
        g_plist[basep + rank] = i;
    }
}

__global__ void scatter_kernel(const void* __restrict__ ei, int E, int nN) {
    int is64 = g_is64;
    int e = blockIdx.x * blockDim.x + threadIdx.x;
    if (e < E) {
        int p = idx_at(ei, e, is64, nN);
        int c = idx_at(ei, E + e, is64, nN);
        int pos = atomicAdd(&g_pos[p], 1);
        g_children[g_row[p] + pos] = c;
    }
}

// ---------------- embedding (packed f32x2, 4 warps/block, 8 nodes/warp) ------
__global__ __launch_bounds__(128) void embed_kernel(
    const float* __restrict__ x, const float* __restrict__ pW, const float* __restrict__ pb,
    const float* __restrict__ eW, const float* __restrict__ eb,
    const float* __restrict__ gamma, const float* __restrict__ beta, int nN)
{
    __shared__ float4 s_pW[10 * 32];
    __shared__ float4 s_eW[2 * 32 * 32];
    __shared__ float4 s_x[4][8][5];
    __shared__ float4 s_h[4][8][16];
    int tid = threadIdx.x;
    for (int i = tid; i < 10 * 32; i += 128) {
        int kp = i >> 5, l = i & 31;
        int k0 = 2 * kp, k1 = 2 * kp + 1;
        float a = (k0 < FIN) ? pW[k0 * 64 + l]      : 0.f;
        float b = (k0 < FIN) ? pW[k0 * 64 + l + 32] : 0.f;
        float c = (k1 < FIN) ? pW[k1 * 64 + l]      : 0.f;
        float d = (k1 < FIN) ? pW[k1 * 64 + l + 32] : 0.f;
        s_pW[i] = make_float4(a, b, c, d);
    }
    for (int i = tid; i < 2 * 32 * 32; i += 128) {
        int li = i >> 10, r = i & 1023, kp = r >> 5, l = r & 31;
        const float* W = eW + li * 4096;
        int k0 = 2 * kp;
        s_eW[i] = make_float4(W[k0 * 64 + l], W[k0 * 64 + l + 32],
                              W[(k0 + 1) * 64 + l], W[(k0 + 1) * 64 + l + 32]);
    }
    __syncthreads();

    int wid = tid >> 5, lane = tid & 31;
    unsigned long long pb2 = pack2(pb[lane], pb[lane + 32]);
    unsigned long long eb2[2];
    float gl[2], ghi[2], bl[2], bh[2];
#pragma unroll
    for (int i2 = 0; i2 < 2; i2++) {
        eb2[i2] = pack2(eb[i2 * 64 + lane], eb[i2 * 64 + lane + 32]);
        gl[i2] = gamma[i2 * 64 + lane];  ghi[i2] = gamma[i2 * 64 + lane + 32];
        bl[i2] = beta[i2 * 64 + lane];   bh[i2] = beta[i2 * 64 + lane + 32];
    }
    float* sxf = (float*)&s_x[wid][0][0];
    float* shf = (float*)&s_h[wid][0][0];

    int nG = (nN + 7) >> 3;
    for (int g = blockIdx.x * 4 + wid; g < nG; g += gridDim.x * 4) {
        int n0 = g << 3;
        int rem = nN - n0;
        size_t base = (size_t)n0 * FIN;
        size_t lim = (size_t)nN * FIN;
        __syncwarp();
#pragma unroll
        for (int t2 = 0; t2 < 5; ++t2) {
            int idx = lane + 32 * t2;
            if (idx < 8 * FIN) {
                float v = (base + idx < lim) ? x[base + idx] : 0.f;
                int r = idx / FIN, kk = idx - r * FIN;
                sxf[r * 20 + kk] = v;
            }
        }
        if (lane < 8) sxf[lane * 20 + 19] = 0.f;
        __syncwarp();

        unsigned long long acc[8];
#pragma unroll
        for (int r = 0; r < 8; r++) acc[r] = pb2;
#pragma unroll
        for (int kq = 0; kq < 5; ++kq) {
            ulonglong2 w0 = *(const ulonglong2*)&s_pW[(2 * kq) * 32 + lane];
            ulonglong2 w1 = *(const ulonglong2*)&s_pW[(2 * kq + 1) * 32 + lane];
#pragma unroll
            for (int r = 0; r < 8; r++) {
                float4 xv = s_x[wid][r][kq];
                fma2(acc[r], w0.x, dup2(xv.x));
                fma2(acc[r], w0.y, dup2(xv.y));
                fma2(acc[r], w1.x, dup2(xv.z));
                fma2(acc[r], w1.y, dup2(xv.w));
            }
        }
        float hl[8], hh[8];
#pragma unroll
        for (int r = 0; r < 8; r++) {
            float a, b; unpack2(acc[r], a, b);
            hl[r] = leaky(a); hh[r] = leaky(b);
        }

#pragma unroll
        for (int li = 0; li < 2; ++li) {
#pragma unroll
            for (int r = 0; r < 8; r++) { shf[r * 64 + lane] = hl[r]; shf[r * 64 + lane + 32] = hh[r]; }
            __syncwarp();
#pragma unroll
            for (int r = 0; r < 8; r++) acc[r] = eb2[li];
#pragma unroll
            for (int kq = 0; kq < 16; ++kq) {
                ulonglong2 w0 = *(const ulonglong2*)&s_eW[li * 1024 + (2 * kq) * 32 + lane];
                ulonglong2 w1 = *(const ulonglong2*)&s_eW[li * 1024 + (2 * kq + 1) * 32 + lane];
#pragma unroll
                for (int r = 0; r < 8; r++) {
                    float4 hv = s_h[wid][r][kq];
                    fma2(acc[r], w0.x, dup2(hv.x));
                    fma2(acc[r], w0.y, dup2(hv.y));
                    fma2(acc[r], w1.x, dup2(hv.z));
                    fma2(acc[r], w1.y, dup2(hv.w));
                }
            }
#pragma unroll
            for (int r = 0; r < 8; r++) {
                float tl, th; unpack2(acc[r], tl, th);
                float ul = hl[r] + leaky(tl);
                float uh = hh[r] + leaky(th);
                float s1 = wsum(ul + uh);
                float s2 = wsum(ul * ul + uh * uh);
                float mu = s1 * (1.f / 64.f);
                float var = s2 * (1.f / 64.f) - mu * mu;
                float inv = rsqrtf(var + LN_EPS);
                hl[r] = (ul - mu) * inv * gl[li] + bl[li];
                hh[r] = (uh - mu) * inv * ghi[li] + bh[li];
            }
            __syncwarp();
        }
#pragma unroll
        for (int r = 0; r < 8; r++) {
            if (r < rem) {
                g_h[(size_t)(n0 + r) * 64 + lane] = hl[r];
                g_h[(size_t)(n0 + r) * 64 + lane + 32] = hh[r];
            }
        }
    }
}

// ------- fused message passing: interleaved gather (MLP=8) + packed MLP ------
__global__ __launch_bounds__(256) void mp_kernel(
    const float* __restrict__ W1g, const float* __restrict__ b1g,
    const float* __restrict__ W2g, const float* __restrict__ b2g)
{
    __shared__ float4 s_W1[1024];
    __shared__ float4 s_W2[1024];
    __shared__ float4 s_hq[8][8][16];
    int tid = threadIdx.x;
    for (int i = tid; i < 1024; i += 256) {
        int kp = i >> 5, l = i & 31; int k0 = kp * 2;
        s_W1[i] = make_float4(W1g[k0 * 64 + l], W1g[k0 * 64 + l + 32],
                              W1g[(k0 + 1) * 64 + l], W1g[(k0 + 1) * 64 + l + 32]);
        s_W2[i] = make_float4(W2g[k0 * 64 + l], W2g[k0 * 64 + l + 32],
                              W2g[(k0 + 1) * 64 + l], W2g[(k0 + 1) * 64 + l + 32]);
    }
    __syncthreads();
    int wid = tid >> 5, lane = tid & 31;
    unsigned long long b12 = pack2(b1g[lane], b1g[lane + 32]);
    unsigned long long b22 = pack2(b2g[lane], b2g[lane + 32]);
    float* shf = (float*)&s_hq[wid][0][0];
    int np = g_nplist;
    int nG = (np + 7) >> 3;
    for (int g = blockIdx.x * 8 + wid; g < nG; g += gridDim.x * 8) {
        int i0 = g << 3;
        __syncwarp();
        // ---- interleaved gather across the 8 parents (8 independent LDGs) ----
        int st[8], cc[8];
        int maxc = 0;
#pragma unroll
        for (int r = 0; r < 8; r++) {
            if (i0 + r < np) {
                int p = g_plist[i0 + r];
                st[r] = g_row[p];
                cc[r] = g_cnt[p];
                maxc = max(maxc, cc[r]);
            } else { st[r] = 0; cc[r] = 0; }
        }
        unsigned long long sum[8];
#pragma unroll
        for (int r = 0; r < 8; r++) sum[r] = 0ull;
        for (int t = 0; t < maxc; ++t) {
            unsigned long long hv[8];
#pragma unroll
            for (int r = 0; r < 8; r++) {
                if (t < cc[r]) {
                    int ch = g_children[st[r] + t];
                    hv[r] = *(const unsigned long long*)(g_h + (size_t)ch * 64 + 2 * lane);
                }
            }
#pragma unroll
            for (int r = 0; r < 8; r++)
                if (t < cc[r]) add2(sum[r], hv[r]);
        }
#pragma unroll
        for (int r = 0; r < 8; r++)
            if (cc[r] > 0) mul2(sum[r], dup2(1.f / (float)cc[r]));
#pragma unroll
        for (int r = 0; r < 8; r++)
            *(unsigned long long*)(shf + r * 64 + 2 * lane) = sum[r];
        __syncwarp();

        unsigned long long acc[8];
#pragma unroll
        for (int r = 0; r < 8; r++) acc[r] = b12;
#pragma unroll
        for (int kq = 0; kq < 16; ++kq) {
            ulonglong2 w0 = *(const ulonglong2*)&s_W1[(2 * kq) * 32 + lane];
            ulonglong2 w1 = *(const ulonglong2*)&s_W1[(2 * kq + 1) * 32 + lane];
#pragma unroll
            for (int r = 0; r < 8; r++) {
                float4 hv = s_hq[wid][r][kq];
                fma2(acc[r], w0.x, dup2(hv.x));
                fma2(acc[r], w0.y, dup2(hv.y));
                fma2(acc[r], w1.x, dup2(hv.z));
                fma2(acc[r], w1.y, dup2(hv.w));
            }
        }
        __syncwarp();
#pragma unroll
        for (int r = 0; r < 8; r++) {
            float a, b; unpack2(acc[r], a, b);
            shf[r * 64 + lane] = leaky(a);
            shf[r * 64 + lane + 32] = leaky(b);
        }
        __syncwarp();
#pragma unroll
        for (int r = 0; r < 8; r++) acc[r] = b22;
#pragma unroll
        for (int kq = 0; kq < 16; ++kq) {
            ulonglong2 w0 = *(const ulonglong2*)&s_W2[(2 * kq) * 32 + lane];
            ulonglong2 w1 = *(const ulonglong2*)&s_W2[(2 * kq + 1) * 32 + lane];
#pragma unroll
            for (int r = 0; r < 8; r++) {
                float4 hv = s_hq[wid][r][kq];
                fma2(acc[r], w0.x, dup2(hv.x));
                fma2(acc[r], w0.y, dup2(hv.y));
                fma2(acc[r], w1.x, dup2(hv.z));
                fma2(acc[r], w1.y, dup2(hv.w));
            }
        }
#pragma unroll
        for (int r = 0; r < 8; r++) {
            if (i0 + r < np) {
                float a, b; unpack2(acc[r], a, b);
                float* d = g_delta + (size_t)(i0 + r) * 64;
                d[lane] = a;
                d[lane + 32] = b;
            }
        }
    }
}

// ---------------- apply: warp per parent, float2 ----------------
__global__ void apply_kernel() {
    int np = g_nplist;
    int lane = threadIdx.x & 31;
    int w = (blockIdx.x * blockDim.x + threadIdx.x) >> 5;
    int nw = (gridDim.x * blockDim.x) >> 5;
    for (int pi = w; pi < np; pi += nw) {
        int p = g_plist[pi];
        const float2* dr = (const float2*)(g_delta + (size_t)pi * 64);
        float2* hr = (float2*)(g_h + (size_t)p * 64);
        float2 d = dr[lane];
        float2 h = hr[lane];
        h.x += d.x; h.y += d.y;
        hr[lane] = h;
    }
}

// ---------------- score head + softmax (single block) ----------------
__global__ __launch_bounds__(256) void head_kernel(
    const void* __restrict__ cand,
    const float* __restrict__ W1g, const float* __restrict__ b1g,
    const float* __restrict__ W2g, const float* __restrict__ b2g,
    float* __restrict__ out, int K, int nN)
{
    __shared__ float4 s_W1[1024];
    __shared__ float4 s_hq[8][4][16];
    __shared__ float s_sc[1024];
    __shared__ float s_red[256];
    int tid = threadIdx.x;
    int is64 = g_is64;
    for (int i = tid; i < 1024; i += 256) {
        int kp = i >> 5, l = i & 31; int k0 = kp * 2;
        s_W1[i] = make_float4(W1g[k0 * 64 + l], W1g[k0 * 64 + l + 32],
                              W1g[(k0 + 1) * 64 + l], W1g[(k0 + 1) * 64 + l + 32]);
    }
    __syncthreads();
    int wid = tid >> 5, lane = tid & 31;
    float b1l = b1g[lane], b1h = b1g[lane + 32];
    float w2l = W2g[lane], w2h = W2g[lane + 32];
    float b2s = b2g[0];
    float* shf = (float*)&s_hq[wid][0][0];
    int nQ = (K + 3) >> 2;
    for (int q = wid; q < nQ; q += 8) {
        int c0 = q << 2;
        __syncwarp();
#pragma unroll
        for (int r = 0; r < 4; r++) {
            if (c0 + r < K) {
                int node = idx_at(cand, c0 + r, is64, nN);
                const float* hr = g_h + (size_t)node * 64;
                shf[r * 64 + lane] = hr[lane];
                shf[r * 64 + lane + 32] = hr[lane + 32];
            } else {
                shf[r * 64 + lane] = 0.f;
                shf[r * 64 + lane + 32] = 0.f;
            }
        }
        __syncwarp();
        float tl[4], th[4];
#pragma unroll
        for (int r = 0; r < 4; r++) { tl[r] = b1l; th[r] = b1h; }
#pragma unroll
        for (int kq = 0; kq < 16; ++kq) {
            float4 w0 = s_W1[(2 * kq) * 32 + lane];
            float4 w1 = s_W1[(2 * kq + 1) * 32 + lane];
#pragma unroll
            for (int r = 0; r < 4; r++) {
                float4 hv = s_hq[wid][r][kq];
                tl[r] += hv.x * w0.x + hv.y * w0.z + hv.z * w1.x + hv.w * w1.z;
                th[r] += hv.x * w0.y + hv.y * w0.w + hv.z * w1.y + hv.w * w1.w;
            }
        }
#pragma unroll
        for (int r = 0; r < 4; r++) {
            float s = leaky(tl[r]) * w2l + leaky(th[r]) * w2h;
            s = wsum(s) + b2s;
            if (lane == 0 && c0 + r < K) s_sc[c0 + r] = s;
        }
    }
    __syncthreads();
    float m = -3.4e38f;
    for (int i = tid; i < K; i += 256) m = fmaxf(m, s_sc[i]);
    s_red[tid] = m; __syncthreads();
    for (int o = 128; o; o >>= 1) { if (tid < o) s_red[tid] = fmaxf(s_red[tid], s_red[tid + o]); __syncthreads(); }
    m = s_red[0];
    __syncthreads();
    float sum = 0.f;
    for (int i = tid; i < K; i += 256) { float e = expf(s_sc[i] - m); s_sc[i] = e; sum += e; }
    s_red[tid] = sum; __syncthreads();
    for (int o = 128; o; o >>= 1) { if (tid < o) s_red[tid] += s_red[tid + o]; __syncthreads(); }
    float invT = 1.f / s_red[0];
    for (int i = tid; i < K; i += 256) out[i] = s_sc[i] * invT;
}

// ---------------- launch ----------------
extern "C" void kernel_launch(void* const* d_in, const int* in_sizes, int n_in,
                              void* d_out, int out_size) {
    const float* x     = (const float*)d_in[0];
    const void*  ei    = d_in[1];
    const void*  cand  = d_in[2];
    const float* pW    = (const float*)d_in[3];
    const float* pb    = (const float*)d_in[4];
    const float* eW    = (const float*)d_in[5];
    const float* eb    = (const float*)d_in[6];
    const float* gamma = (const float*)d_in[7];
    const float* beta  = (const float*)d_in[8];
    const float* sW1   = (const float*)d_in[9];
    const float* sb1   = (const float*)d_in[10];
    const float* sW2   = (const float*)d_in[11];
    const float* sb2   = (const float*)d_in[12];
    const float* hW1   = (const float*)d_in[13];
    const float* hb1   = (const float*)d_in[14];
    const float* hW2   = (const float*)d_in[15];
    const float* hb2   = (const float*)d_in[16];

    int nN = in_sizes[0] / FIN;
    int E  = in_sizes[1] / 2;
    int K  = in_sizes[2];

    int nb256 = (nN + 255) / 256;
    int eb256 = (E + 255) / 256;
    int scanBlocks = (nN + 1023) / 1024;

    // launch order arranged so the 4th launch (ncu capture slot) is embed_kernel
    detect_kernel<<<1, 256>>>((const unsigned*)ei, E);          // 0
    zero_kernel<<<nb256, 256>>>(nN);                            // 1
    hist_kernel<<<eb256, 256>>>(ei, E, nN);                     // 2
    embed_kernel<<<592, 128>>>(x, pW, pb, eW, eb, gamma, beta, nN); // 3 <- profiled
    scan_cnt_kernel<<<scanBlocks, 256>>>(nN);                   // 4
    scan_bsum_kernel<<<1, 256>>>(scanBlocks);                   // 5
    addback_kernel<<<nb256, 256>>>(nN);                         // 6
    scatter_kernel<<<eb256, 256>>>(ei, E, nN);                  // 7

    for (int it = 0; it < 3; ++it) {
        mp_kernel<<<592, 256>>>(sW1 + it * 4096, sb1 + it * 64,
                                sW2 + it * 4096, sb2 + it * 64);
        apply_kernel<<<2048, 256>>>();
    }

    head_kernel<<<1, 256>>>(cand, hW1, hb1, hW2, hb2, (float*)d_out, K, nN);
}